// round 3
// baseline (speedup 1.0000x reference)
#include <cuda_runtime.h>
#include <math.h>

#define BB 4
#define LL 2048
#define LQ 1024
#define DM 512
#define DIN 1024
#define DSTATE 64
#define NH 16
#define HD 64
#define DXBC 1152
#define ZXW 2176      // z + xBC columns kept in g_zx (row stride)
#define WIN_LD 2192   // full in_proj width (z + xBC + dt)

// ---------------- scratch (device globals; allocation-free) ----------------
__device__ float g_u[2][BB*LL*DM];        // rmsnormed inputs
__device__ float g_zx[2][BB*LL*ZXW];      // in_proj outputs (z + xBC)
__device__ float g_xbc[2][BB*LL*DXBC];    // conv+silu outputs
__device__ float g_dt[2][BB*LL*NH];
__device__ float g_dA[2][BB*LL*NH];
__device__ float g_y[2][BB*LL*DIN];       // scan outputs (+D*x)
__device__ float g_nrm[2][BB*LQ*DIN];     // gated rmsnorm (last LQ tokens only)
__device__ float g_fs[BB*LQ*DM];          // factual block output before out proj

// ---------------- helpers ----------------
__device__ __forceinline__ float silu(float x) { return x / (1.f + expf(-x)); }

// ---------------- 1) input rmsnorm (concat + optional flip) ----------------
__global__ void prep_norm(const float* __restrict__ q, const float* __restrict__ kv,
                          const float* __restrict__ fw, const float* __restrict__ cw)
{
    int row = blockIdx.x;            // 2 * 4 * 2048 rows
    int br  = row >> 13;
    int r   = row & 8191;
    int b   = r >> 11;
    int l   = r & 2047;
    const float* src;
    if (l < LQ) {
        int li = (br == 0) ? l : (LQ - 1 - l);   // counterfactual flips kv
        src = kv + (b * LQ + li) * DM;
    } else {
        src = q + (b * LQ + (l - LQ)) * DM;
    }
    const float* w = br ? cw : fw;

    int t = threadIdx.x;             // 128
    float v[4];
    float ss = 0.f;
#pragma unroll
    for (int i = 0; i < 4; i++) { v[i] = src[t + i * 128]; ss += v[i] * v[i]; }

    __shared__ float red[4];
#pragma unroll
    for (int o = 16; o > 0; o >>= 1) ss += __shfl_xor_sync(0xffffffffu, ss, o);
    if ((t & 31) == 0) red[t >> 5] = ss;
    __syncthreads();
    float total = red[0] + red[1] + red[2] + red[3];
    float scale = rsqrtf(total / (float)DM + 1e-5f);

    float* dst = g_u[br] + (b * LL + l) * DM;
#pragma unroll
    for (int i = 0; i < 4; i++) {
        int idx = t + i * 128;
        dst[idx] = v[i] * scale * w[idx];
    }
}

// ---------------- 2) SGEMM 128x128x8, 256 threads, 8x8/thread -------------
template<bool BIAS>
__global__ void sgemm128(const float* __restrict__ A, const float* __restrict__ B,
                         float* __restrict__ C, const float* __restrict__ bias,
                         int M, int N, int K, int lda, int ldb, int ldc)
{
    __shared__ float As[8][128];
    __shared__ float Bs[8][128];
    int tid = threadIdx.x;
    int bm = blockIdx.y * 128, bn = blockIdx.x * 128;

    int arow = tid >> 1, acol = (tid & 1) * 4;
    int brow = tid >> 5, bcol = (tid & 31) * 4;
    int ty = tid >> 4, tx = tid & 15;

    const float* Aptr = A + (bm + arow) * lda + acol;
    const float* Bptr = B + brow * ldb + bn + bcol;

    float acc[8][8];
#pragma unroll
    for (int i = 0; i < 8; i++)
#pragma unroll
        for (int j = 0; j < 8; j++) acc[i][j] = 0.f;

    for (int k0 = 0; k0 < K; k0 += 8) {
        float4 av = *(const float4*)Aptr; Aptr += 8;
        float4 bv = *(const float4*)Bptr; Bptr += 8 * ldb;
        As[acol + 0][arow] = av.x;
        As[acol + 1][arow] = av.y;
        As[acol + 2][arow] = av.z;
        As[acol + 3][arow] = av.w;
        *(float4*)&Bs[brow][bcol] = bv;
        __syncthreads();
#pragma unroll
        for (int k = 0; k < 8; k++) {
            float af[8], bf[8];
#pragma unroll
            for (int i = 0; i < 8; i++) af[i] = As[k][ty * 8 + i];
#pragma unroll
            for (int j = 0; j < 8; j++) bf[j] = Bs[k][tx * 8 + j];
#pragma unroll
            for (int i = 0; i < 8; i++)
#pragma unroll
                for (int j = 0; j < 8; j++) acc[i][j] += af[i] * bf[j];
        }
        __syncthreads();
    }

#pragma unroll
    for (int i = 0; i < 8; i++) {
        int row = bm + ty * 8 + i;
        float* crow = C + row * ldc + bn + tx * 8;
#pragma unroll
        for (int j = 0; j < 8; j++) {
            float v = acc[i][j];
            if (BIAS) v += bias[bn + tx * 8 + j];
            crow[j] = v;
        }
    }
}

// ---------------- 3) causal depthwise conv + silu -------------------------
__global__ void conv_silu(int br, const float* __restrict__ w, const float* __restrict__ bias)
{
    int idx = blockIdx.x * 256 + threadIdx.x;
    if (idx >= BB * LL * DXBC) return;
    int c = idx % DXBC;
    int l = (idx / DXBC) % LL;
    int b = idx / (DXBC * LL);
    const float* zb = g_zx[br] + (b * LL) * ZXW + DIN + c;
    float s = bias[c];
#pragma unroll
    for (int j = 0; j < 4; j++) {
        int ls = l - 3 + j;
        if (ls >= 0) s += zb[ls * ZXW] * w[c * 4 + j];
    }
    g_xbc[br][idx] = silu(s);
}

// ---------------- 4) dt GEMM (N=16 tail of Win) + softplus + dA -----------
// block: 256 threads = 16 rows x 16 heads; Win slice (512x16) in smem
__global__ void __launch_bounds__(256) dt_gemm(int br, const float* __restrict__ u,
                                               const float* __restrict__ Win,
                                               const float* __restrict__ dtb,
                                               const float* __restrict__ Alog)
{
    __shared__ float Ws[512][16];
    int tid = threadIdx.x;
    // load Win[:, 2176:2192] into smem
    for (int i = tid; i < 512 * 16; i += 256) {
        int k = i >> 4, h = i & 15;
        Ws[k][h] = Win[k * WIN_LD + ZXW + h];
    }
    __syncthreads();

    int rib = tid >> 4;      // row in block (0..15)
    int h   = tid & 15;
    int row = blockIdx.x * 16 + rib;          // 0 .. BB*LL-1
    const float* arow = u + row * DM;

    float acc = dtb[h];
#pragma unroll 8
    for (int k = 0; k < 512; k++) acc += arow[k] * Ws[k][h];

    float dt = acc > 20.f ? acc : log1pf(expf(acc));
    int idx = row * NH + h;
    g_dt[br][idx] = dt;
    g_dA[br][idx] = expf(-expf(Alog[h]) * dt);
}

// ---------------- 5) SSD sequential scan ----------------------------------
__global__ void __launch_bounds__(512) scan_kernel(const float* __restrict__ fD,
                                                   const float* __restrict__ cD)
{
    int blk = blockIdx.x;            // 128 = 2 * 4 * 16
    int br = blk >> 6;
    int r = blk & 63;
    int b = r >> 4;
    int h = r & 15;
    const float* xbc = g_xbc[br];
    const float* dtp = g_dt[br];
    const float* dAp = g_dA[br];
    const float* Dp  = br ? cD : fD;
    float* yp = g_y[br];

    __shared__ float xs[2][64], bs[2][64], cs_[2][64], sc[2][2];

    int t = threadIdx.x;             // 512
    int p = t >> 3;
    int nb = (t & 7) << 3;
    float Dh = Dp[h];

    float hreg[8];
#pragma unroll
    for (int j = 0; j < 8; j++) hreg[j] = 0.f;

    int rowbase = b * LL;

    float pre = 0.f;
    {
        int off = rowbase * DXBC;
        if (t < 64)        pre = xbc[off + h * 64 + t];
        else if (t < 128)  pre = xbc[off + 1024 + (t - 64)];
        else if (t < 192)  pre = xbc[off + 1088 + (t - 128)];
        else if (t == 192) pre = dtp[rowbase * NH + h];
        else if (t == 193) pre = dAp[rowbase * NH + h];
    }

    int cur = 0;
    for (int l = 0; l < LL; l++) {
        if (t < 64)       xs[cur][t] = pre;
        else if (t < 128) bs[cur][t - 64] = pre;
        else if (t < 192) cs_[cur][t - 128] = pre;
        else if (t < 194) sc[cur][t - 192] = pre;
        __syncthreads();

        if (l + 1 < LL) {
            int off = (rowbase + l + 1) * DXBC;
            if (t < 64)        pre = xbc[off + h * 64 + t];
            else if (t < 128)  pre = xbc[off + 1024 + (t - 64)];
            else if (t < 192)  pre = xbc[off + 1088 + (t - 128)];
            else if (t == 192) pre = dtp[(rowbase + l + 1) * NH + h];
            else if (t == 193) pre = dAp[(rowbase + l + 1) * NH + h];
        }

        float dtv = sc[cur][0], dav = sc[cur][1];
        float xv = xs[cur][p];
        float dtx = dtv * xv;
        float acc = 0.f;
#pragma unroll
        for (int j = 0; j < 8; j++) {
            hreg[j] = hreg[j] * dav + dtx * bs[cur][nb + j];
            acc += hreg[j] * cs_[cur][nb + j];
        }
        acc += __shfl_xor_sync(0xffffffffu, acc, 1);
        acc += __shfl_xor_sync(0xffffffffu, acc, 2);
        acc += __shfl_xor_sync(0xffffffffu, acc, 4);
        if ((t & 7) == 0)
            yp[(rowbase + l) * DIN + h * HD + p] = acc + Dh * xv;
        cur ^= 1;
    }
}

// ---------------- 6) y * silu(z) + rmsnorm (last LQ tokens) ----------------
__global__ void yz_norm(const float* __restrict__ fnw, const float* __restrict__ cnw)
{
    int row = blockIdx.x;            // 2 * 4 * 1024
    int br = row >> 12;
    int r = row & 4095;
    int b = r >> 10;
    int lq = r & 1023;
    int l = lq + LQ;
    const float* nw = br ? cnw : fnw;
    const float* yrow = g_y[br] + (b * LL + l) * DIN;
    const float* zrow = g_zx[br] + (b * LL + l) * ZXW;

    int t = threadIdx.x;             // 256
    float v[4];
    float ss = 0.f;
#pragma unroll
    for (int i = 0; i < 4; i++) {
        int idx = t + i * 256;
        float z = zrow[idx];
        float val = yrow[idx] * silu(z);
        v[i] = val;
        ss += val * val;
    }

    __shared__ float red[8];
#pragma unroll
    for (int o = 16; o > 0; o >>= 1) ss += __shfl_xor_sync(0xffffffffu, ss, o);
    if ((t & 31) == 0) red[t >> 5] = ss;
    __syncthreads();
    float total = 0.f;
#pragma unroll
    for (int i = 0; i < 8; i++) total += red[i];
    float scale = rsqrtf(total / (float)DIN + 1e-5f);

    float* dst = g_nrm[br] + ((b << 10) + lq) * DIN;
#pragma unroll
    for (int i = 0; i < 4; i++) {
        int idx = t + i * 256;
        dst[idx] = v[i] * scale * nw[idx];
    }
}

// ---------------- launch ----------------------------------------------------
extern "C" void kernel_launch(void* const* d_in, const int* in_sizes, int n_in,
                              void* d_out, int out_size)
{
    const float* query   = (const float*)d_in[0];
    const float* kv      = (const float*)d_in[1];
    const float* fnorm_w = (const float*)d_in[2];
    const float* cnorm_w = (const float*)d_in[3];
    const float* f_Win   = (const float*)d_in[4];
    const float* f_convw = (const float*)d_in[5];
    const float* f_convb = (const float*)d_in[6];
    const float* f_dtb   = (const float*)d_in[7];
    const float* f_Alog  = (const float*)d_in[8];
    const float* f_D     = (const float*)d_in[9];
    const float* f_normw = (const float*)d_in[10];
    const float* f_Wout  = (const float*)d_in[11];
    const float* c_Win   = (const float*)d_in[12];
    const float* c_convw = (const float*)d_in[13];
    const float* c_convb = (const float*)d_in[14];
    const float* c_dtb   = (const float*)d_in[15];
    const float* c_Alog  = (const float*)d_in[16];
    const float* c_D     = (const float*)d_in[17];
    const float* c_normw = (const float*)d_in[18];
    const float* c_Wout  = (const float*)d_in[19];
    const float* outp_w  = (const float*)d_in[20];
    const float* outp_b  = (const float*)d_in[21];
    float* out = (float*)d_out;

    float *uP, *zxP, *nrmP, *fsP;
    cudaGetSymbolAddress((void**)&uP,   g_u);
    cudaGetSymbolAddress((void**)&zxP,  g_zx);
    cudaGetSymbolAddress((void**)&nrmP, g_nrm);
    cudaGetSymbolAddress((void**)&fsP,  g_fs);

    float* u_f  = uP;
    float* u_c  = uP + BB * LL * DM;
    float* zx_f = zxP;
    float* zx_c = zxP + BB * LL * ZXW;
    float* nrm_f = nrmP;
    float* nrm_c = nrmP + BB * LQ * DIN;

    // 1) input rmsnorm for both branches
    prep_norm<<<2 * BB * LL, 128>>>(query, kv, fnorm_w, cnorm_w);

    // 2) in_proj GEMMs: (8192 x 512) @ (512 x 2176) [dt cols handled separately]
    {
        dim3 grid(ZXW / 128, (BB * LL) / 128);
        sgemm128<false><<<grid, 256>>>(u_f, f_Win, zx_f, nullptr, BB * LL, ZXW, DM, DM, WIN_LD, ZXW);
        sgemm128<false><<<grid, 256>>>(u_c, c_Win, zx_c, nullptr, BB * LL, ZXW, DM, DM, WIN_LD, ZXW);
    }

    // 3) conv + silu
    {
        int total = BB * LL * DXBC;
        int blocks = (total + 255) / 256;
        conv_silu<<<blocks, 256>>>(0, f_convw, f_convb);
        conv_silu<<<blocks, 256>>>(1, c_convw, c_convb);
    }

    // 4) dt columns + softplus + dA
    {
        int blocks = (BB * LL) / 16;
        dt_gemm<<<blocks, 256>>>(0, u_f, f_Win, f_dtb, f_Alog);
        dt_gemm<<<blocks, 256>>>(1, u_c, c_Win, c_dtb, c_Alog);
    }

    // 5) sequential scan, both branches in one grid
    scan_kernel<<<128, 512>>>(f_D, c_D);

    // 6) gate + rmsnorm (only the output slice)
    yz_norm<<<2 * BB * LQ, 256>>>(f_normw, c_normw);

    // 7) out-projection GEMMs: (4096 x 1024) @ (1024 x 512)
    {
        dim3 grid(DM / 128, (BB * LQ) / 128);
        sgemm128<false><<<grid, 256>>>(nrm_f, f_Wout, fsP, nullptr, BB * LQ, DM, DIN, DIN, DM, DM);
        sgemm128<false><<<grid, 256>>>(nrm_c, c_Wout, out + BB * LQ * DM, nullptr, BB * LQ, DM, DIN, DIN, DM, DM);
    }

    // 8) factual final projection with bias: (4096 x 512) @ (512 x 512) + b
    {
        dim3 grid(DM / 128, (BB * LQ) / 128);
        sgemm128<true><<<grid, 256>>>(fsP, outp_w, out, outp_b, BB * LQ, DM, DM, DM, DM, DM);
    }
}

// round 4
// speedup vs baseline: 1.5345x; 1.5345x over previous
#include <cuda_runtime.h>
#include <math.h>
#include <stdint.h>

#define BB 4
#define LL 2048
#define LQ 1024
#define DM 512
#define DIN 1024
#define DSTATE 64
#define NH 16
#define HD 64
#define DXBC 1152
#define ZXW 2176      // z + xBC columns kept in g_zx (row stride)
#define WIN_LD 2192   // full in_proj width (z + xBC + dt)

// ---------------- scratch (device globals; allocation-free) ----------------
__device__ float g_u[2][BB*LL*DM];        // rmsnormed inputs
__device__ float g_zx[2][BB*LL*ZXW];      // in_proj outputs (z + xBC)
__device__ float g_xbc[2][BB*LL*DXBC];    // conv+silu outputs
__device__ float g_dt[2][BB*LL*NH];
__device__ float g_dA[2][BB*LL*NH];
__device__ float g_y[2][BB*LL*DIN];       // scan outputs (+D*x)
__device__ float g_nrm[2][BB*LQ*DIN];     // gated rmsnorm (last LQ tokens only)
__device__ float g_fs[BB*LQ*DM];          // factual block output before out proj

// ---------------- helpers ----------------
__device__ __forceinline__ float silu(float x) { return x / (1.f + expf(-x)); }

__device__ __forceinline__ uint32_t f2tf32(float x) {
    uint32_t r;
    asm("cvt.rna.tf32.f32 %0, %1;" : "=r"(r) : "f"(x));
    return r;
}

__device__ __forceinline__ void mma_tf32(float* c, const uint32_t* a, const uint32_t* b) {
    asm volatile("mma.sync.aligned.m16n8k8.row.col.f32.tf32.tf32.f32 "
        "{%0,%1,%2,%3}, {%4,%5,%6,%7}, {%8,%9}, {%0,%1,%2,%3};"
        : "+f"(c[0]), "+f"(c[1]), "+f"(c[2]), "+f"(c[3])
        : "r"(a[0]), "r"(a[1]), "r"(a[2]), "r"(a[3]), "r"(b[0]), "r"(b[1]));
}

// ---------------- 1) input rmsnorm (concat + optional flip) ----------------
__global__ void prep_norm(const float* __restrict__ q, const float* __restrict__ kv,
                          const float* __restrict__ fw, const float* __restrict__ cw)
{
    int row = blockIdx.x;            // 2 * 4 * 2048 rows
    int br  = row >> 13;
    int r   = row & 8191;
    int b   = r >> 11;
    int l   = r & 2047;
    const float* src;
    if (l < LQ) {
        int li = (br == 0) ? l : (LQ - 1 - l);   // counterfactual flips kv
        src = kv + (b * LQ + li) * DM;
    } else {
        src = q + (b * LQ + (l - LQ)) * DM;
    }
    const float* w = br ? cw : fw;

    int t = threadIdx.x;             // 128
    float v[4];
    float ss = 0.f;
#pragma unroll
    for (int i = 0; i < 4; i++) { v[i] = src[t + i * 128]; ss += v[i] * v[i]; }

    __shared__ float red[4];
#pragma unroll
    for (int o = 16; o > 0; o >>= 1) ss += __shfl_xor_sync(0xffffffffu, ss, o);
    if ((t & 31) == 0) red[t >> 5] = ss;
    __syncthreads();
    float total = red[0] + red[1] + red[2] + red[3];
    float scale = rsqrtf(total / (float)DM + 1e-5f);

    float* dst = g_u[br] + (b * LL + l) * DM;
#pragma unroll
    for (int i = 0; i < 4; i++) {
        int idx = t + i * 128;
        dst[idx] = v[i] * scale * w[idx];
    }
}

// ---------------- 2) TF32 tensor-core GEMM: 128x128x32 tile, 8 warps ------
// A row-major MxK, B row-major KxN, C row-major MxN.
#define AS_LD 36
#define BS_LD 136
template<bool BIAS>
__global__ void __launch_bounds__(256) gemm_tf32(
    const float* __restrict__ A, const float* __restrict__ B,
    float* __restrict__ C, const float* __restrict__ bias,
    int M, int N, int K, int lda, int ldb, int ldc)
{
    __shared__ uint32_t As[128 * AS_LD];  // [m][k], stride 36
    __shared__ uint32_t Bs[32 * BS_LD];   // [k][n], stride 136

    int tid = threadIdx.x;
    int bm = blockIdx.y * 128, bn = blockIdx.x * 128;

    int w = tid >> 5;
    int lane = tid & 31;
    int g = lane >> 2, cq = lane & 3;
    int mw = (w & 1) * 64;      // warp m offset
    int nw = (w >> 1) * 32;     // warp n offset

    // global load mapping
    int a_r = tid >> 3, a_c4 = (tid & 7) * 4;       // A: rows a_r + rr*32, cols a_c4..+3
    int b_r = tid >> 5, b_c4 = (tid & 31) * 4;      // B: rows b_r + rr*8, cols b_c4..+3

    const float* Ag = A + (bm + a_r) * lda + a_c4;
    const float* Bg = B + b_r * ldb + bn + b_c4;

    float acc[4][4][4];
#pragma unroll
    for (int i = 0; i < 4; i++)
#pragma unroll
        for (int j = 0; j < 4; j++)
#pragma unroll
            for (int x = 0; x < 4; x++) acc[i][j][x] = 0.f;

    for (int kt = 0; kt < K; kt += 32) {
        // load + convert A tile (128x32)
#pragma unroll
        for (int rr = 0; rr < 4; rr++) {
            float4 v = *(const float4*)(Ag + rr * 32 * lda + kt);
            uint32_t* d = &As[(a_r + rr * 32) * AS_LD + a_c4];
            d[0] = f2tf32(v.x); d[1] = f2tf32(v.y); d[2] = f2tf32(v.z); d[3] = f2tf32(v.w);
        }
        // load + convert B tile (32x128)
#pragma unroll
        for (int rr = 0; rr < 4; rr++) {
            float4 v = *(const float4*)(Bg + (kt + rr * 8) * ldb);
            uint32_t* d = &Bs[(b_r + rr * 8) * BS_LD + b_c4];
            d[0] = f2tf32(v.x); d[1] = f2tf32(v.y); d[2] = f2tf32(v.z); d[3] = f2tf32(v.w);
        }
        __syncthreads();

#pragma unroll
        for (int ks = 0; ks < 4; ks++) {
            int k0 = ks * 8;
            uint32_t af[4][4], bf[4][2];
#pragma unroll
            for (int i = 0; i < 4; i++) {
                int m = mw + i * 16 + g;
                af[i][0] = As[m * AS_LD + k0 + cq];
                af[i][1] = As[(m + 8) * AS_LD + k0 + cq];
                af[i][2] = As[m * AS_LD + k0 + cq + 4];
                af[i][3] = As[(m + 8) * AS_LD + k0 + cq + 4];
            }
#pragma unroll
            for (int j = 0; j < 4; j++) {
                int n = nw + j * 8 + g;
                bf[j][0] = Bs[(k0 + cq) * BS_LD + n];
                bf[j][1] = Bs[(k0 + cq + 4) * BS_LD + n];
            }
#pragma unroll
            for (int i = 0; i < 4; i++)
#pragma unroll
                for (int j = 0; j < 4; j++)
                    mma_tf32(acc[i][j], af[i], bf[j]);
        }
        __syncthreads();
    }

    // epilogue
#pragma unroll
    for (int i = 0; i < 4; i++) {
        int m0 = bm + mw + i * 16 + g;
#pragma unroll
        for (int j = 0; j < 4; j++) {
            int n = bn + nw + j * 8 + 2 * cq;
            float b0 = 0.f, b1 = 0.f;
            if (BIAS) { b0 = bias[n]; b1 = bias[n + 1]; }
            float2 v0 = { acc[i][j][0] + b0, acc[i][j][1] + b1 };
            float2 v1 = { acc[i][j][2] + b0, acc[i][j][3] + b1 };
            *(float2*)&C[m0 * ldc + n] = v0;
            *(float2*)&C[(m0 + 8) * ldc + n] = v1;
        }
    }
}

// ---------------- 3) causal depthwise conv + silu -------------------------
__global__ void conv_silu(int br, const float* __restrict__ w, const float* __restrict__ bias)
{
    int idx = blockIdx.x * 256 + threadIdx.x;
    if (idx >= BB * LL * DXBC) return;
    int c = idx % DXBC;
    int l = (idx / DXBC) % LL;
    int b = idx / (DXBC * LL);
    const float* zb = g_zx[br] + (b * LL) * ZXW + DIN + c;
    float s = bias[c];
#pragma unroll
    for (int j = 0; j < 4; j++) {
        int ls = l - 3 + j;
        if (ls >= 0) s += zb[ls * ZXW] * w[c * 4 + j];
    }
    g_xbc[br][idx] = silu(s);
}

// ---------------- 4) dt GEMM (N=16 tail of Win) + softplus + dA -----------
__global__ void __launch_bounds__(256) dt_gemm(int br, const float* __restrict__ u,
                                               const float* __restrict__ Win,
                                               const float* __restrict__ dtb,
                                               const float* __restrict__ Alog)
{
    __shared__ float Ws[512][16];
    int tid = threadIdx.x;
    for (int i = tid; i < 512 * 16; i += 256) {
        int k = i >> 4, h = i & 15;
        Ws[k][h] = Win[k * WIN_LD + ZXW + h];
    }
    __syncthreads();

    int rib = tid >> 4;
    int h   = tid & 15;
    int row = blockIdx.x * 16 + rib;
    const float* arow = u + row * DM;

    float acc = dtb[h];
#pragma unroll 8
    for (int k = 0; k < 512; k++) acc += arow[k] * Ws[k][h];

    float dt = acc > 20.f ? acc : log1pf(expf(acc));
    int idx = row * NH + h;
    g_dt[br][idx] = dt;
    g_dA[br][idx] = expf(-expf(Alog[h]) * dt);
}

// ---------------- 5) SSD sequential scan ----------------------------------
__global__ void __launch_bounds__(512) scan_kernel(const float* __restrict__ fD,
                                                   const float* __restrict__ cD)
{
    int blk = blockIdx.x;            // 128 = 2 * 4 * 16
    int br = blk >> 6;
    int r = blk & 63;
    int b = r >> 4;
    int h = r & 15;
    const float* xbc = g_xbc[br];
    const float* dtp = g_dt[br];
    const float* dAp = g_dA[br];
    const float* Dp  = br ? cD : fD;
    float* yp = g_y[br];

    __shared__ float xs[2][64], bs[2][64], cs_[2][64], sc[2][2];

    int t = threadIdx.x;             // 512
    int p = t >> 3;
    int nb = (t & 7) << 3;
    float Dh = Dp[h];

    float hreg[8];
#pragma unroll
    for (int j = 0; j < 8; j++) hreg[j] = 0.f;

    int rowbase = b * LL;

    float pre = 0.f;
    {
        int off = rowbase * DXBC;
        if (t < 64)        pre = xbc[off + h * 64 + t];
        else if (t < 128)  pre = xbc[off + 1024 + (t - 64)];
        else if (t < 192)  pre = xbc[off + 1088 + (t - 128)];
        else if (t == 192) pre = dtp[rowbase * NH + h];
        else if (t == 193) pre = dAp[rowbase * NH + h];
    }

    int cur = 0;
    for (int l = 0; l < LL; l++) {
        if (t < 64)       xs[cur][t] = pre;
        else if (t < 128) bs[cur][t - 64] = pre;
        else if (t < 192) cs_[cur][t - 128] = pre;
        else if (t < 194) sc[cur][t - 192] = pre;
        __syncthreads();

        if (l + 1 < LL) {
            int off = (rowbase + l + 1) * DXBC;
            if (t < 64)        pre = xbc[off + h * 64 + t];
            else if (t < 128)  pre = xbc[off + 1024 + (t - 64)];
            else if (t < 192)  pre = xbc[off + 1088 + (t - 128)];
            else if (t == 192) pre = dtp[(rowbase + l + 1) * NH + h];
            else if (t == 193) pre = dAp[(rowbase + l + 1) * NH + h];
        }

        float dtv = sc[cur][0], dav = sc[cur][1];
        float xv = xs[cur][p];
        float dtx = dtv * xv;
        float acc = 0.f;
#pragma unroll
        for (int j = 0; j < 8; j++) {
            hreg[j] = hreg[j] * dav + dtx * bs[cur][nb + j];
            acc += hreg[j] * cs_[cur][nb + j];
        }
        acc += __shfl_xor_sync(0xffffffffu, acc, 1);
        acc += __shfl_xor_sync(0xffffffffu, acc, 2);
        acc += __shfl_xor_sync(0xffffffffu, acc, 4);
        if ((t & 7) == 0)
            yp[(rowbase + l) * DIN + h * HD + p] = acc + Dh * xv;
        cur ^= 1;
    }
}

// ---------------- 6) y * silu(z) + rmsnorm (last LQ tokens) ----------------
__global__ void yz_norm(const float* __restrict__ fnw, const float* __restrict__ cnw)
{
    int row = blockIdx.x;            // 2 * 4 * 1024
    int br = row >> 12;
    int r = row & 4095;
    int b = r >> 10;
    int lq = r & 1023;
    int l = lq + LQ;
    const float* nw = br ? cnw : fnw;
    const float* yrow = g_y[br] + (b * LL + l) * DIN;
    const float* zrow = g_zx[br] + (b * LL + l) * ZXW;

    int t = threadIdx.x;             // 256
    float v[4];
    float ss = 0.f;
#pragma unroll
    for (int i = 0; i < 4; i++) {
        int idx = t + i * 256;
        float z = zrow[idx];
        float val = yrow[idx] * silu(z);
        v[i] = val;
        ss += val * val;
    }

    __shared__ float red[8];
#pragma unroll
    for (int o = 16; o > 0; o >>= 1) ss += __shfl_xor_sync(0xffffffffu, ss, o);
    if ((t & 31) == 0) red[t >> 5] = ss;
    __syncthreads();
    float total = 0.f;
#pragma unroll
    for (int i = 0; i < 8; i++) total += red[i];
    float scale = rsqrtf(total / (float)DIN + 1e-5f);

    float* dst = g_nrm[br] + ((b << 10) + lq) * DIN;
#pragma unroll
    for (int i = 0; i < 4; i++) {
        int idx = t + i * 256;
        dst[idx] = v[i] * scale * nw[idx];
    }
}

// ---------------- launch ----------------------------------------------------
extern "C" void kernel_launch(void* const* d_in, const int* in_sizes, int n_in,
                              void* d_out, int out_size)
{
    const float* query   = (const float*)d_in[0];
    const float* kv      = (const float*)d_in[1];
    const float* fnorm_w = (const float*)d_in[2];
    const float* cnorm_w = (const float*)d_in[3];
    const float* f_Win   = (const float*)d_in[4];
    const float* f_convw = (const float*)d_in[5];
    const float* f_convb = (const float*)d_in[6];
    const float* f_dtb   = (const float*)d_in[7];
    const float* f_Alog  = (const float*)d_in[8];
    const float* f_D     = (const float*)d_in[9];
    const float* f_normw = (const float*)d_in[10];
    const float* f_Wout  = (const float*)d_in[11];
    const float* c_Win   = (const float*)d_in[12];
    const float* c_convw = (const float*)d_in[13];
    const float* c_convb = (const float*)d_in[14];
    const float* c_dtb   = (const float*)d_in[15];
    const float* c_Alog  = (const float*)d_in[16];
    const float* c_D     = (const float*)d_in[17];
    const float* c_normw = (const float*)d_in[18];
    const float* c_Wout  = (const float*)d_in[19];
    const float* outp_w  = (const float*)d_in[20];
    const float* outp_b  = (const float*)d_in[21];
    float* out = (float*)d_out;

    float *uP, *zxP, *nrmP, *fsP;
    cudaGetSymbolAddress((void**)&uP,   g_u);
    cudaGetSymbolAddress((void**)&zxP,  g_zx);
    cudaGetSymbolAddress((void**)&nrmP, g_nrm);
    cudaGetSymbolAddress((void**)&fsP,  g_fs);

    float* u_f  = uP;
    float* u_c  = uP + BB * LL * DM;
    float* zx_f = zxP;
    float* zx_c = zxP + BB * LL * ZXW;
    float* nrm_f = nrmP;
    float* nrm_c = nrmP + BB * LQ * DIN;

    // 1) input rmsnorm for both branches
    prep_norm<<<2 * BB * LL, 128>>>(query, kv, fnorm_w, cnorm_w);

    // 2) in_proj GEMMs (tf32 tensor cores): (8192 x 512) @ (512 x 2176)
    {
        dim3 grid(ZXW / 128, (BB * LL) / 128);
        gemm_tf32<false><<<grid, 256>>>(u_f, f_Win, zx_f, nullptr, BB * LL, ZXW, DM, DM, WIN_LD, ZXW);
        gemm_tf32<false><<<grid, 256>>>(u_c, c_Win, zx_c, nullptr, BB * LL, ZXW, DM, DM, WIN_LD, ZXW);
    }

    // 3) conv + silu
    {
        int total = BB * LL * DXBC;
        int blocks = (total + 255) / 256;
        conv_silu<<<blocks, 256>>>(0, f_convw, f_convb);
        conv_silu<<<blocks, 256>>>(1, c_convw, c_convb);
    }

    // 4) dt columns + softplus + dA (fp32, precision-sensitive)
    {
        int blocks = (BB * LL) / 16;
        dt_gemm<<<blocks, 256>>>(0, u_f, f_Win, f_dtb, f_Alog);
        dt_gemm<<<blocks, 256>>>(1, u_c, c_Win, c_dtb, c_Alog);
    }

    // 5) sequential scan, both branches in one grid
    scan_kernel<<<128, 512>>>(f_D, c_D);

    // 6) gate + rmsnorm (only the output slice)
    yz_norm<<<2 * BB * LQ, 256>>>(f_normw, c_normw);

    // 7) out-projection GEMMs: (4096 x 1024) @ (1024 x 512)
    {
        dim3 grid(DM / 128, (BB * LQ) / 128);
        gemm_tf32<false><<<grid, 256>>>(nrm_f, f_Wout, fsP, nullptr, BB * LQ, DM, DIN, DIN, DM, DM);
        gemm_tf32<false><<<grid, 256>>>(nrm_c, c_Wout, out + BB * LQ * DM, nullptr, BB * LQ, DM, DIN, DIN, DM, DM);
    }

    // 8) factual final projection with bias: (4096 x 512) @ (512 x 512) + b
    {
        dim3 grid(DM / 128, (BB * LQ) / 128);
        gemm_tf32<true><<<grid, 256>>>(fsP, outp_w, out, outp_b, BB * LQ, DM, DM, DM, DM, DM);
    }
}

// round 7
// speedup vs baseline: 2.4814x; 1.6171x over previous
#include <cuda_runtime.h>
#include <math.h>
#include <stdint.h>

#define BB 4
#define LL 2048
#define LQ 1024
#define DM 512
#define DIN 1024
#define DSTATE 64
#define NH 16
#define HD 64
#define DXBC 1152
#define ZXW 2176      // z + xBC columns kept in g_zx (row stride)
#define WIN_LD 2192   // full in_proj width (z + xBC + dt)

// ---------------- scratch (device globals; allocation-free) ----------------
__device__ float g_u[2][BB*LL*DM];        // rmsnormed inputs (fp32, for dt path)
__device__ float g_u32[2][BB*LL*DM];      // rmsnormed inputs (tf32-rounded, GEMM A)
__device__ float g_zx[2][BB*LL*ZXW];      // in_proj outputs (z + xBC)
__device__ float g_xbc[2][BB*LL*DXBC];    // conv+silu outputs
__device__ float g_dt[2][BB*LL*NH];
__device__ float g_dA[2][BB*LL*NH];
__device__ float g_y[2][BB*LL*DIN];       // scan outputs (+D*x)
__device__ float g_nrm[2][BB*LQ*DIN];     // gated rmsnorm (tf32-rounded)
__device__ float g_fs[BB*LQ*DM];          // factual pre-out-proj (tf32-rounded)
__device__ float g_win32[2][DM*ZXW];      // tf32 weights
__device__ float g_wout32[2][DIN*DM];
__device__ float g_wo32[DM*DM];

// ---------------- helpers ----------------
__device__ __forceinline__ float silu(float x) { return x / (1.f + expf(-x)); }

__device__ __forceinline__ uint32_t f2tf32(float x) {
    uint32_t r;
    asm("cvt.rna.tf32.f32 %0, %1;" : "=r"(r) : "f"(x));
    return r;
}
__device__ __forceinline__ float tf32r(float x) { return __uint_as_float(f2tf32(x)); }

__device__ __forceinline__ void mma_tf32(float* c, const uint32_t* a, const uint32_t* b) {
    asm volatile("mma.sync.aligned.m16n8k8.row.col.f32.tf32.tf32.f32 "
        "{%0,%1,%2,%3}, {%4,%5,%6,%7}, {%8,%9}, {%0,%1,%2,%3};"
        : "+f"(c[0]), "+f"(c[1]), "+f"(c[2]), "+f"(c[3])
        : "r"(a[0]), "r"(a[1]), "r"(a[2]), "r"(a[3]), "r"(b[0]), "r"(b[1]));
}

__device__ __forceinline__ void cpa16(float* dst, const float* src) {
    uint32_t d = (uint32_t)__cvta_generic_to_shared(dst);
    asm volatile("cp.async.cg.shared.global [%0], [%1], 16;" :: "r"(d), "l"(src));
}
__device__ __forceinline__ void cpa_commit() { asm volatile("cp.async.commit_group;"); }
template<int N> __device__ __forceinline__ void cpa_wait() {
    asm volatile("cp.async.wait_group %0;" :: "n"(N));
}

// ---------------- 0) weight tf32 conversion -------------------------------
__global__ void cvt_tf32_k(const float* __restrict__ src, float* __restrict__ dst,
                           int n, int width, int srcld)
{
    int i = blockIdx.x * 256 + threadIdx.x;
    if (i >= n) return;
    int r = i / width, c = i - r * width;
    dst[i] = tf32r(src[r * srcld + c]);
}

// ---------------- 1) input rmsnorm (concat + optional flip) ----------------
__global__ void prep_norm(const float* __restrict__ q, const float* __restrict__ kv,
                          const float* __restrict__ fw, const float* __restrict__ cw)
{
    int row = blockIdx.x;            // 2 * 4 * 2048 rows
    int br  = row >> 13;
    int r   = row & 8191;
    int b   = r >> 11;
    int l   = r & 2047;
    const float* src;
    if (l < LQ) {
        int li = (br == 0) ? l : (LQ - 1 - l);
        src = kv + (b * LQ + li) * DM;
    } else {
        src = q + (b * LQ + (l - LQ)) * DM;
    }
    const float* w = br ? cw : fw;

    int t = threadIdx.x;             // 128
    float v[4];
    float ss = 0.f;
#pragma unroll
    for (int i = 0; i < 4; i++) { v[i] = src[t + i * 128]; ss += v[i] * v[i]; }

    __shared__ float red[4];
#pragma unroll
    for (int o = 16; o > 0; o >>= 1) ss += __shfl_xor_sync(0xffffffffu, ss, o);
    if ((t & 31) == 0) red[t >> 5] = ss;
    __syncthreads();
    float total = red[0] + red[1] + red[2] + red[3];
    float scale = rsqrtf(total / (float)DM + 1e-5f);

    float* dst   = g_u[br]   + (b * LL + l) * DM;
    float* dst32 = g_u32[br] + (b * LL + l) * DM;
#pragma unroll
    for (int i = 0; i < 4; i++) {
        int idx = t + i * 128;
        float val = v[i] * scale * w[idx];
        dst[idx] = val;
        dst32[idx] = tf32r(val);
    }
}

// ---------------- 2) TF32 GEMM, cp.async 3-stage pipeline ------------------
// A row-major MxK (pre-tf32), B row-major KxN (pre-tf32), C row-major MxN.
#define AS_LD 36
#define BS_LD 136
#define A_STG (128 * AS_LD)    // 4608 floats
#define B_STG (32 * BS_LD)     // 4352 floats
#define B_OFF (3 * A_STG)
#define GEMM_SMEM ((3 * (A_STG + B_STG)) * 4)

__global__ void __launch_bounds__(256) gemm_tf32(
    const float* __restrict__ A0, const float* __restrict__ A1,
    const float* __restrict__ B0, const float* __restrict__ B1,
    float* __restrict__ C0, float* __restrict__ C1,
    const float* __restrict__ bias,
    int M, int N, int K, int lda, int ldb, int ldc, int roundMask)
{
    extern __shared__ float sm[];
    int z = blockIdx.z;
    const float* A = z ? A1 : A0;
    const float* B = z ? B1 : B0;
    float* C = z ? C1 : C0;
    bool rnd = (roundMask >> z) & 1;

    int tid = threadIdx.x;
    int bm = blockIdx.y * 128, bn = blockIdx.x * 128;

    int w = tid >> 5;
    int lane = tid & 31;
    int g = lane >> 2, cq = lane & 3;
    int mw = (w & 1) * 64;
    int nw = (w >> 1) * 32;

    int a_r = tid >> 3, a_c4 = (tid & 7) * 4;
    int b_r = tid >> 5, b_c4 = (tid & 31) * 4;

    const float* Ag = A + (bm + a_r) * lda + a_c4;
    const float* Bg = B + b_r * ldb + bn + b_c4;

    int nk = K >> 5;

    // prologue: prefetch stages 0,1
#pragma unroll
    for (int st = 0; st < 2; st++) {
        float* As = sm + st * A_STG;
        float* Bs = sm + B_OFF + st * B_STG;
#pragma unroll
        for (int rr = 0; rr < 4; rr++)
            cpa16(&As[(a_r + rr * 32) * AS_LD + a_c4], Ag + rr * 32 * lda + st * 32);
#pragma unroll
        for (int rr = 0; rr < 4; rr++)
            cpa16(&Bs[(b_r + rr * 8) * BS_LD + b_c4], Bg + (st * 32 + rr * 8) * ldb);
        cpa_commit();
    }

    float acc[4][4][4];
#pragma unroll
    for (int i = 0; i < 4; i++)
#pragma unroll
        for (int j = 0; j < 4; j++)
#pragma unroll
            for (int x = 0; x < 4; x++) acc[i][j][x] = 0.f;

    for (int kt = 0; kt < nk; kt++) {
        if (kt + 1 < nk) cpa_wait<1>(); else cpa_wait<0>();
        __syncthreads();

        if (kt + 2 < nk) {
            int st = (kt + 2) % 3;
            float* As = sm + st * A_STG;
            float* Bs = sm + B_OFF + st * B_STG;
            int k0 = (kt + 2) * 32;
#pragma unroll
            for (int rr = 0; rr < 4; rr++)
                cpa16(&As[(a_r + rr * 32) * AS_LD + a_c4], Ag + rr * 32 * lda + k0);
#pragma unroll
            for (int rr = 0; rr < 4; rr++)
                cpa16(&Bs[(b_r + rr * 8) * BS_LD + b_c4], Bg + (k0 + rr * 8) * ldb);
            cpa_commit();
        }

        const float* As = sm + (kt % 3) * A_STG;
        const float* Bs = sm + B_OFF + (kt % 3) * B_STG;
#pragma unroll
        for (int ks = 0; ks < 4; ks++) {
            int k0 = ks * 8;
            uint32_t af[4][4], bf[4][2];
#pragma unroll
            for (int i = 0; i < 4; i++) {
                int m = mw + i * 16 + g;
                af[i][0] = __float_as_uint(As[m * AS_LD + k0 + cq]);
                af[i][1] = __float_as_uint(As[(m + 8) * AS_LD + k0 + cq]);
                af[i][2] = __float_as_uint(As[m * AS_LD + k0 + cq + 4]);
                af[i][3] = __float_as_uint(As[(m + 8) * AS_LD + k0 + cq + 4]);
            }
#pragma unroll
            for (int j = 0; j < 4; j++) {
                int n = nw + j * 8 + g;
                bf[j][0] = __float_as_uint(Bs[(k0 + cq) * BS_LD + n]);
                bf[j][1] = __float_as_uint(Bs[(k0 + cq + 4) * BS_LD + n]);
            }
#pragma unroll
            for (int i = 0; i < 4; i++)
#pragma unroll
                for (int j = 0; j < 4; j++)
                    mma_tf32(acc[i][j], af[i], bf[j]);
        }
    }

    // epilogue
#pragma unroll
    for (int i = 0; i < 4; i++) {
        int m0 = bm + mw + i * 16 + g;
#pragma unroll
        for (int j = 0; j < 4; j++) {
            int n = bn + nw + j * 8 + 2 * cq;
            float b0 = 0.f, b1 = 0.f;
            if (bias) { b0 = bias[n]; b1 = bias[n + 1]; }
            float v00 = acc[i][j][0] + b0, v01 = acc[i][j][1] + b1;
            float v10 = acc[i][j][2] + b0, v11 = acc[i][j][3] + b1;
            if (rnd) { v00 = tf32r(v00); v01 = tf32r(v01); v10 = tf32r(v10); v11 = tf32r(v11); }
            float2 lo = { v00, v01 }, hi = { v10, v11 };
            *(float2*)&C[m0 * ldc + n] = lo;
            *(float2*)&C[(m0 + 8) * ldc + n] = hi;
        }
    }
}

// ---------------- 3) causal depthwise conv + silu (both branches) ----------
__global__ void conv_silu(const float* __restrict__ fw, const float* __restrict__ fb,
                          const float* __restrict__ cw_, const float* __restrict__ cb)
{
    int br = blockIdx.y;
    const float* w = br ? cw_ : fw;
    const float* bias = br ? cb : fb;
    int idx = blockIdx.x * 256 + threadIdx.x;
    if (idx >= BB * LL * DXBC) return;
    int c = idx % DXBC;
    int l = (idx / DXBC) % LL;
    int b = idx / (DXBC * LL);
    const float* zb = g_zx[br] + (b * LL) * ZXW + DIN + c;
    float s = bias[c];
#pragma unroll
    for (int j = 0; j < 4; j++) {
        int ls = l - 3 + j;
        if (ls >= 0) s += zb[ls * ZXW] * w[c * 4 + j];
    }
    g_xbc[br][idx] = silu(s);
}

// ---------------- 4) dt GEMM (fp32) + softplus + dA (both branches) --------
__global__ void __launch_bounds__(256) dt_gemm(
    const float* __restrict__ fWin, const float* __restrict__ cWin,
    const float* __restrict__ fdtb, const float* __restrict__ cdtb,
    const float* __restrict__ fAl,  const float* __restrict__ cAl)
{
    int br = blockIdx.y;
    const float* Win = br ? cWin : fWin;
    const float* dtb = br ? cdtb : fdtb;
    const float* Alog = br ? cAl : fAl;
    const float* u = g_u[br];

    __shared__ float Ws[512][16];
    int tid = threadIdx.x;
    for (int i = tid; i < 512 * 16; i += 256) {
        int k = i >> 4, h = i & 15;
        Ws[k][h] = Win[k * WIN_LD + ZXW + h];
    }
    __syncthreads();

    int rib = tid >> 4;
    int h   = tid & 15;
    int row = blockIdx.x * 16 + rib;
    const float* arow = u + row * DM;

    float a0 = 0.f, a1 = 0.f, a2 = 0.f, a3 = 0.f;
#pragma unroll 4
    for (int k = 0; k < 512; k += 4) {
        a0 += arow[k]     * Ws[k][h];
        a1 += arow[k + 1] * Ws[k + 1][h];
        a2 += arow[k + 2] * Ws[k + 2][h];
        a3 += arow[k + 3] * Ws[k + 3][h];
    }
    float acc = dtb[h] + ((a0 + a1) + (a2 + a3));

    float dt = acc > 20.f ? acc : log1pf(expf(acc));
    int idx = row * NH + h;
    g_dt[br][idx] = dt;
    g_dA[br][idx] = expf(-expf(Alog[h]) * dt);
}

// ---------------- 5) SSD sequential scan, 8-step chunks --------------------
#define CH 8
__global__ void __launch_bounds__(512) scan_kernel(const float* __restrict__ fD,
                                                   const float* __restrict__ cD)
{
    int blk = blockIdx.x;            // 128 = 2 * 4 * 16
    int br = blk >> 6;
    int r = blk & 63;
    int b = r >> 4;
    int h = r & 15;
    const float* xbc = g_xbc[br];
    const float* dtp = g_dt[br];
    const float* dAp = g_dA[br];
    const float* Dp  = br ? cD : fD;
    float* yp = g_y[br];

    __shared__ float xs[2][CH][64], bs[2][CH][64], cs_[2][CH][64], sc[2][CH][2];

    int t = threadIdx.x;             // 512
    int p = t >> 3;
    int nb = (t & 7) << 3;
    int step = t >> 6, slot = t & 63;
    float Dh = Dp[h];

    float hreg[8];
#pragma unroll
    for (int j = 0; j < 8; j++) hreg[j] = 0.f;

    int rowbase = b * LL;

    float rx, rb, rc, rs = 0.f;
    {
        const float* base = xbc + (rowbase + step) * DXBC;
        rx = base[h * 64 + slot];
        rb = base[1024 + slot];
        rc = base[1088 + slot];
        if (t < 8)       rs = dtp[(rowbase + t) * NH + h];
        else if (t < 16) rs = dAp[(rowbase + (t - 8)) * NH + h];
    }

    int cur = 0;
    for (int c = 0; c < LL / CH; c++) {
        xs[cur][step][slot]  = rx;
        bs[cur][step][slot]  = rb;
        cs_[cur][step][slot] = rc;
        if (t < 8)       sc[cur][t][0] = rs;
        else if (t < 16) sc[cur][t - 8][1] = rs;
        __syncthreads();

        if (c + 1 < LL / CH) {
            int l0n = (c + 1) * CH;
            const float* base = xbc + (rowbase + l0n + step) * DXBC;
            rx = base[h * 64 + slot];
            rb = base[1024 + slot];
            rc = base[1088 + slot];
            if (t < 8)       rs = dtp[(rowbase + l0n + t) * NH + h];
            else if (t < 16) rs = dAp[(rowbase + l0n + (t - 8)) * NH + h];
        }

        int l0 = c * CH;
#pragma unroll
        for (int s = 0; s < CH; s++) {
            float dtv = sc[cur][s][0], dav = sc[cur][s][1];
            float xv = xs[cur][s][p];
            float dtx = dtv * xv;
            float4 b0 = *(const float4*)&bs[cur][s][nb];
            float4 b1 = *(const float4*)&bs[cur][s][nb + 4];
            float4 c0 = *(const float4*)&cs_[cur][s][nb];
            float4 c1 = *(const float4*)&cs_[cur][s][nb + 4];
            float acc;
            hreg[0] = hreg[0] * dav + dtx * b0.x; acc  = hreg[0] * c0.x;
            hreg[1] = hreg[1] * dav + dtx * b0.y; acc += hreg[1] * c0.y;
            hreg[2] = hreg[2] * dav + dtx * b0.z; acc += hreg[2] * c0.z;
            hreg[3] = hreg[3] * dav + dtx * b0.w; acc += hreg[3] * c0.w;
            hreg[4] = hreg[4] * dav + dtx * b1.x; acc += hreg[4] * c1.x;
            hreg[5] = hreg[5] * dav + dtx * b1.y; acc += hreg[5] * c1.y;
            hreg[6] = hreg[6] * dav + dtx * b1.z; acc += hreg[6] * c1.z;
            hreg[7] = hreg[7] * dav + dtx * b1.w; acc += hreg[7] * c1.w;
            acc += __shfl_xor_sync(0xffffffffu, acc, 1);
            acc += __shfl_xor_sync(0xffffffffu, acc, 2);
            acc += __shfl_xor_sync(0xffffffffu, acc, 4);
            if ((t & 7) == 0)
                yp[(rowbase + l0 + s) * DIN + h * HD + p] = acc + Dh * xv;
        }
        cur ^= 1;
    }
}

// ---------------- 6) y * silu(z) + rmsnorm (last LQ tokens, tf32 out) ------
__global__ void yz_norm(const float* __restrict__ fnw, const float* __restrict__ cnw)
{
    int row = blockIdx.x;            // 2 * 4 * 1024
    int br = row >> 12;
    int r = row & 4095;
    int b = r >> 10;
    int lq = r & 1023;
    int l = lq + LQ;
    const float* nw = br ? cnw : fnw;
    const float* yrow = g_y[br] + (b * LL + l) * DIN;
    const float* zrow = g_zx[br] + (b * LL + l) * ZXW;

    int t = threadIdx.x;             // 256
    float v[4];
    float ss = 0.f;
#pragma unroll
    for (int i = 0; i < 4; i++) {
        int idx = t + i * 256;
        float z = zrow[idx];
        float val = yrow[idx] * silu(z);
        v[i] = val;
        ss += val * val;
    }

    __shared__ float red[8];
#pragma unroll
    for (int o = 16; o > 0; o >>= 1) ss += __shfl_xor_sync(0xffffffffu, ss, o);
    if ((t & 31) == 0) red[t >> 5] = ss;
    __syncthreads();
    float total = 0.f;
#pragma unroll
    for (int i = 0; i < 8; i++) total += red[i];
    float scale = rsqrtf(total / (float)DIN + 1e-5f);

    float* dst = g_nrm[br] + ((b << 10) + lq) * DIN;
#pragma unroll
    for (int i = 0; i < 4; i++) {
        int idx = t + i * 256;
        dst[idx] = tf32r(v[i] * scale * nw[idx]);
    }
}

// ---------------- launch ----------------------------------------------------
extern "C" void kernel_launch(void* const* d_in, const int* in_sizes, int n_in,
                              void* d_out, int out_size)
{
    const float* query   = (const float*)d_in[0];
    const float* kv      = (const float*)d_in[1];
    const float* fnorm_w = (const float*)d_in[2];
    const float* cnorm_w = (const float*)d_in[3];
    const float* f_Win   = (const float*)d_in[4];
    const float* f_convw = (const float*)d_in[5];
    const float* f_convb = (const float*)d_in[6];
    const float* f_dtb   = (const float*)d_in[7];
    const float* f_Alog  = (const float*)d_in[8];
    const float* f_D     = (const float*)d_in[9];
    const float* f_normw = (const float*)d_in[10];
    const float* f_Wout  = (const float*)d_in[11];
    const float* c_Win   = (const float*)d_in[12];
    const float* c_convw = (const float*)d_in[13];
    const float* c_convb = (const float*)d_in[14];
    const float* c_dtb   = (const float*)d_in[15];
    const float* c_Alog  = (const float*)d_in[16];
    const float* c_D     = (const float*)d_in[17];
    const float* c_normw = (const float*)d_in[18];
    const float* c_Wout  = (const float*)d_in[19];
    const float* outp_w  = (const float*)d_in[20];
    const float* outp_b  = (const float*)d_in[21];
    float* out = (float*)d_out;

    float *uP32, *zxP, *nrmP, *fsP, *win32P, *wout32P, *wo32P;
    cudaGetSymbolAddress((void**)&uP32,   g_u32);
    cudaGetSymbolAddress((void**)&zxP,    g_zx);
    cudaGetSymbolAddress((void**)&nrmP,   g_nrm);
    cudaGetSymbolAddress((void**)&fsP,    g_fs);
    cudaGetSymbolAddress((void**)&win32P, g_win32);
    cudaGetSymbolAddress((void**)&wout32P,g_wout32);
    cudaGetSymbolAddress((void**)&wo32P,  g_wo32);

    cudaFuncSetAttribute(gemm_tf32, cudaFuncAttributeMaxDynamicSharedMemorySize, GEMM_SMEM);

    float* u32_f = uP32;
    float* u32_c = uP32 + BB * LL * DM;
    float* zx_f = zxP;
    float* zx_c = zxP + BB * LL * ZXW;
    float* nrm_f = nrmP;
    float* nrm_c = nrmP + BB * LQ * DIN;
    float* win_f = win32P;
    float* win_c = win32P + DM * ZXW;
    float* wout_f = wout32P;
    float* wout_c = wout32P + DIN * DM;

    // 0) weight conversions to tf32
    {
        int nwin = DM * ZXW;
        cvt_tf32_k<<<(nwin + 255) / 256, 256>>>(f_Win, win_f, nwin, ZXW, WIN_LD);
        cvt_tf32_k<<<(nwin + 255) / 256, 256>>>(c_Win, win_c, nwin, ZXW, WIN_LD);
        int nwo = DIN * DM;
        cvt_tf32_k<<<(nwo + 255) / 256, 256>>>(f_Wout, wout_f, nwo, DM, DM);
        cvt_tf32_k<<<(nwo + 255) / 256, 256>>>(c_Wout, wout_c, nwo, DM, DM);
        int nop = DM * DM;
        cvt_tf32_k<<<(nop + 255) / 256, 256>>>(outp_w, wo32P, nop, DM, DM);
    }

    // 1) input rmsnorm for both branches
    prep_norm<<<2 * BB * LL, 128>>>(query, kv, fnorm_w, cnorm_w);

    // 2) in_proj GEMMs (both branches, one launch): (8192 x 512) @ (512 x 2176)
    {
        dim3 grid(ZXW / 128, (BB * LL) / 128, 2);
        gemm_tf32<<<grid, 256, GEMM_SMEM>>>(u32_f, u32_c, win_f, win_c, zx_f, zx_c,
                                            nullptr, BB * LL, ZXW, DM, DM, ZXW, ZXW, 0);
    }

    // 3) conv + silu (both branches)
    {
        int total = BB * LL * DXBC;
        dim3 grid((total + 255) / 256, 2);
        conv_silu<<<grid, 256>>>(f_convw, f_convb, c_convw, c_convb);
    }

    // 4) dt columns + softplus + dA (fp32, both branches)
    {
        dim3 grid((BB * LL) / 16, 2);
        dt_gemm<<<grid, 256>>>(f_Win, c_Win, f_dtb, c_dtb, f_Alog, c_Alog);
    }

    // 5) sequential scan, both branches in one grid
    scan_kernel<<<128, 512>>>(f_D, c_D);

    // 6) gate + rmsnorm (only the output slice)
    yz_norm<<<2 * BB * LQ, 256>>>(f_normw, c_normw);

    // 7) out-projection GEMMs (both branches): (4096 x 1024) @ (1024 x 512)
    //    factual -> g_fs (tf32-rounded), counterfactual -> out[1]
    {
        dim3 grid(DM / 128, (BB * LQ) / 128, 2);
        gemm_tf32<<<grid, 256, GEMM_SMEM>>>(nrm_f, nrm_c, wout_f, wout_c,
                                            fsP, out + BB * LQ * DM,
                                            nullptr, BB * LQ, DM, DIN, DIN, DM, DM, 1);
    }

    // 8) factual final projection with bias: (4096 x 512) @ (512 x 512) + b
    {
        dim3 grid(DM / 128, (BB * LQ) / 128, 1);
        gemm_tf32<<<grid, 256, GEMM_SMEM>>>(fsP, fsP, wo32P, wo32P, out, out,
                                            outp_b, BB * LQ, DM, DM, DM, DM, DM, 0);
    }
}